// round 8
// baseline (speedup 1.0000x reference)
#include <cuda_runtime.h>
#include <cuda_fp16.h>
#include <math.h>
#include <stdint.h>

#define BATCH 32
#define SEQ   2048
#define DIM   1024

#define BM 128
#define BN 256
#define BKH 64                      // k elems per chunk (A: 256B fp32 rows, B: 128B fp16 rows)
#define KCHUNKS (DIM / BKH)         // 16
#define STAGES 3
#define ROWH 72                     // halfs per fp16 smem row (LDSM conflict-free)
#define ROWF 68                     // floats per fp32 staging row (272B, 16B-aligned)

// smem layout (bytes)
#define A32_BYTES (BM * ROWF * 4)            // 34816 (single stage)
#define A16_BYTES (BM * ROWH * 2)            // 18432 per stage
#define B16_BYTES (BN * ROWH * 2)            // 36864 per stage
#define OFF_A32   0
#define OFF_A16(s) (A32_BYTES + (s) * A16_BYTES)
#define OFF_B16(s) (A32_BYTES + STAGES * A16_BYTES + (s) * B16_BYTES)
#define OFF_QV    (A32_BYTES + STAGES * (A16_BYTES + B16_BYTES))
#define SMEM_BYTES (OFF_QV + 2 * BN * 4)     // ~202.8 KB

// Scratch (static __device__ — no allocation inside kernel_launch)
__device__ float  g_q[BATCH * DIM];
__device__ float  g_scores[BATCH * SEQ];
__device__ __half g_U_h[DIM * DIM];          // fp16 copy of Uw (prep)

__device__ __forceinline__ uint32_t smem_u32(const void* p) {
    uint32_t a;
    asm("{ .reg .u64 t; cvta.to.shared.u64 t, %1; cvt.u32.u64 %0, t; }"
        : "=r"(a) : "l"(p));
    return a;
}

__device__ __forceinline__ void cp16(uint32_t dst, const void* src) {
    asm volatile("cp.async.cg.shared.global [%0], [%1], 16;"
                 :: "r"(dst), "l"(src) : "memory");
}
#define CP_COMMIT()  asm volatile("cp.async.commit_group;" ::: "memory")
#define CP_WAIT_ALL() asm volatile("cp.async.wait_all;" ::: "memory")

__device__ __forceinline__ void ldm_x4(uint32_t r[4], uint32_t addr) {
    asm volatile("ldmatrix.sync.aligned.m8n8.x4.shared.b16 {%0,%1,%2,%3}, [%4];"
                 : "=r"(r[0]), "=r"(r[1]), "=r"(r[2]), "=r"(r[3]) : "r"(addr));
}

__device__ __forceinline__ void mma_f16(float c[4], const uint32_t a[4], const uint32_t b[2]) {
    asm volatile(
        "mma.sync.aligned.m16n8k16.row.col.f32.f16.f16.f32 "
        "{%0,%1,%2,%3}, {%4,%5,%6,%7}, {%8,%9}, {%0,%1,%2,%3};"
        : "+f"(c[0]), "+f"(c[1]), "+f"(c[2]), "+f"(c[3])
        : "r"(a[0]), "r"(a[1]), "r"(a[2]), "r"(a[3]), "r"(b[0]), "r"(b[1]));
}

// ---------------------------------------------------------------------------
// Kernel 0 (prep, now tiny): U fp32->fp16, q' projection, zero g_scores.
// ---------------------------------------------------------------------------
#define NU8 ((size_t)DIM * DIM / 8)                    // 131072
#define NUCONV_BLOCKS ((unsigned)((NU8 + 255) / 256))  // 512
#define NQP_BLOCKS    (BATCH * DIM / 8)                // 4096

__global__ void prep_kernel(const float* __restrict__ Uw,
                            const float* __restrict__ dh,
                            const float* __restrict__ Ww,
                            const float* __restrict__ Wb,
                            const float* __restrict__ Ub) {
    if (blockIdx.x < NUCONV_BLOCKS) {
        size_t k = (size_t)blockIdx.x * 256 + threadIdx.x;
        if (k >= NU8) return;
        const float4* src = (const float4*)Uw;
        float4 f0 = src[k * 2], f1 = src[k * 2 + 1];
        __half2 h[4];
        h[0] = __floats2half2_rn(f0.x, f0.y);
        h[1] = __floats2half2_rn(f0.z, f0.w);
        h[2] = __floats2half2_rn(f1.x, f1.y);
        h[3] = __floats2half2_rn(f1.z, f1.w);
        ((uint4*)g_U_h)[k] = *(uint4*)h;
        return;
    }
    int qgid = (int)(blockIdx.x - NUCONV_BLOCKS) * 256 + threadIdx.x;
    if (qgid < BATCH * SEQ) g_scores[qgid] = 0.f;

    int warp = qgid >> 5;
    int lane = threadIdx.x & 31;
    if (warp >= BATCH * DIM) return;
    int b = warp / DIM, d = warp % DIM;
    const float* x = dh + b * DIM;
    const float* w = Ww + (size_t)d * DIM;
    float s = 0.f;
    #pragma unroll 4
    for (int e = lane; e < DIM; e += 32) s += x[e] * w[e];
    #pragma unroll
    for (int o = 16; o; o >>= 1) s += __shfl_xor_sync(0xffffffffu, s, o);
    if (lane == 0) g_q[warp] = s + Wb[d] + Ub[d];
}

// ---------------------------------------------------------------------------
// Kernel 2 (dominant): fp16 mma m16n8k16 with IN-KERNEL A conversion.
// A (enc, fp32) streams through a single-stage fp32 staging buffer, is
// converted to the 3-stage fp16 tile by idle issue slots, B (U) is fp16 from
// prep. Fused tanh*v epilogue, atomic score partials.
// Grid (4, 16, 32), 512 threads = 16 warps (4m x 4n), warp tile 32x64.
//
// Per-iter kc: wait-all (A32 kc+1, B kc+1 arrived) -> sync ->
//   convert A32(kc+1) -> A16[(kc+1)%3] -> sync ->
//   issue {A32 kc+2, B16[(kc+2)%3] <- kc+2} -> mma on A16[kc%3], B16[kc%3].
// ---------------------------------------------------------------------------
__global__ __launch_bounds__(512, 1)
void score_kernel(const float* __restrict__ enc,
                  const float* __restrict__ vw) {
    extern __shared__ char smc[];
    const uint32_t sb = smem_u32(smc);

    const int tid  = threadIdx.x;
    const int wid  = tid >> 5;
    const int lane = tid & 31;
    const int wm   = wid & 3;
    const int wn   = wid >> 2;
    const int gr   = lane >> 2;
    const int gc   = lane & 3;

    const int n0 = blockIdx.x * BN;
    const int l0 = blockIdx.y * BM;
    const int b  = blockIdx.z;

    const float*  Abase = enc + ((size_t)b * SEQ + l0) * DIM;
    const __half* Bbase = g_U_h + (size_t)n0 * DIM;

    float* q_sh = (float*)(smc + OFF_QV);
    float* v_sh = q_sh + BN;
    if (tid < BN) {
        q_sh[tid] = g_q[b * DIM + n0 + tid];
        v_sh[tid] = vw[n0 + tid];
    }

    // A32 cp.async mapping: 4 threads per row, 16 floats (4 x 16B) each
    const int arow = tid >> 2;            // 0..127
    const int aseg = (tid & 3) * 16;      // float offset in row
    // B16 cp.async mapping: 8 x 16B segments per 128B row, 64 rows per pass
    const int brow = tid >> 3;            // 0..63
    const int bseg = (tid & 7) * 8;       // half offset in row

    // conversion mapping: thread converts 16 floats of one row quarter
    const int vrow = tid >> 2;
    const int vq   = (tid & 3) * 16;

    const uint32_t a32 = sb + OFF_A32;

    // ---- prologue ----
    // group P0: A32 chunk 0
    #pragma unroll
    for (int s4 = 0; s4 < 4; s4++)
        cp16(a32 + (arow * ROWF + aseg + s4 * 4) * 4, Abase + (size_t)arow * DIM + aseg + s4 * 4);
    CP_COMMIT();
    CP_WAIT_ALL();
    __syncthreads();
    // convert chunk 0 -> A16[0]
    {
        const float* src = (const float*)(smc + OFF_A32) + vrow * ROWF + vq;
        __half2 h[8];
        #pragma unroll
        for (int j = 0; j < 8; j++) h[j] = __floats2half2_rn(src[j * 2], src[j * 2 + 1]);
        uint4* dst = (uint4*)(smc + OFF_A16(0) + (vrow * ROWH + vq) * 2);
        dst[0] = *(uint4*)&h[0];
        dst[1] = *(uint4*)&h[4];
    }
    __syncthreads();
    // group P1: A32 chunk 1 + B chunks 0,1
    #pragma unroll
    for (int s4 = 0; s4 < 4; s4++)
        cp16(a32 + (arow * ROWF + aseg + s4 * 4) * 4,
             Abase + (size_t)arow * DIM + BKH + aseg + s4 * 4);
    #pragma unroll
    for (int s = 0; s < 2; s++) {
        const uint32_t bst = sb + OFF_B16(s);
        #pragma unroll
        for (int r = 0; r < 4; r++) {
            int row = brow + r * 64;
            cp16(bst + (row * ROWH + bseg) * 2, Bbase + (size_t)row * DIM + s * BKH + bseg);
        }
    }
    CP_COMMIT();

    // ldmatrix lane address components
    const int a_row = (lane & 7) + ((lane >> 3) & 1) * 8;
    const int a_col = ((lane >> 4) & 1) * 8;
    const int b_row = (lane & 7) + ((lane >> 4) & 1) * 8;
    const int b_col = ((lane >> 3) & 1) * 8;

    float acc[2][8][4];
    #pragma unroll
    for (int i = 0; i < 2; i++)
        #pragma unroll
        for (int j = 0; j < 8; j++)
            #pragma unroll
            for (int r = 0; r < 4; r++) acc[i][j][r] = 0.f;

    for (int kc = 0; kc < KCHUNKS; kc++) {
        CP_WAIT_ALL();
        __syncthreads();

        // convert A32 (chunk kc+1) -> A16[(kc+1)%3]
        if (kc + 1 < KCHUNKS) {
            const float* src = (const float*)(smc + OFF_A32) + vrow * ROWF + vq;
            __half2 h[8];
            #pragma unroll
            for (int j = 0; j < 8; j++) h[j] = __floats2half2_rn(src[j * 2], src[j * 2 + 1]);
            uint4* dst = (uint4*)(smc + OFF_A16((kc + 1) % STAGES) + (vrow * ROWH + vq) * 2);
            dst[0] = *(uint4*)&h[0];
            dst[1] = *(uint4*)&h[4];
        }
        __syncthreads();

        // issue next chunk's loads
        const int kn = kc + 2;
        if (kn < KCHUNKS) {
            const int kf = kn * BKH;
            #pragma unroll
            for (int s4 = 0; s4 < 4; s4++)
                cp16(a32 + (arow * ROWF + aseg + s4 * 4) * 4,
                     Abase + (size_t)arow * DIM + kf + aseg + s4 * 4);
            const uint32_t bst = sb + OFF_B16(kn % STAGES);
            #pragma unroll
            for (int r = 0; r < 4; r++) {
                int row = brow + r * 64;
                cp16(bst + (row * ROWH + bseg) * 2, Bbase + (size_t)row * DIM + kf + bseg);
            }
            CP_COMMIT();
        }

        // mma on chunk kc
        const uint32_t aoff = sb + OFF_A16(kc % STAGES) + ((wm * 32 + a_row) * ROWH + a_col) * 2;
        const uint32_t boff = sb + OFF_B16(kc % STAGES) + ((wn * 64 + b_row) * ROWH + b_col) * 2;

        #pragma unroll
        for (int ks = 0; ks < 4; ks++) {
            const int kb = ks * 16;
            uint32_t af[2][4], bq[4][4];
            #pragma unroll
            for (int p = 0; p < 4; p++)
                ldm_x4(bq[p], boff + (p * 16 * ROWH + kb) * 2);
            #pragma unroll
            for (int i = 0; i < 2; i++)
                ldm_x4(af[i], aoff + (i * 16 * ROWH + kb) * 2);
            #pragma unroll
            for (int i = 0; i < 2; i++)
                #pragma unroll
                for (int j = 0; j < 8; j++)
                    mma_f16(acc[i][j], af[i], &bq[j >> 1][(j & 1) * 2]);
        }
    }

    // Fused epilogue: reduce 256-wide d-chunk through tanh * v
    #pragma unroll
    for (int i = 0; i < 2; i++) {
        float slo = 0.f, shi = 0.f;
        #pragma unroll
        for (int j = 0; j < 8; j++) {
            const int c = wn * 64 + j * 8 + gc * 2;
            const float v0 = v_sh[c], v1 = v_sh[c + 1];
            const float q0 = q_sh[c], q1 = q_sh[c + 1];
            float x0 = q0 + acc[i][j][0], x1 = q1 + acc[i][j][1];
            float x2 = q0 + acc[i][j][2], x3 = q1 + acc[i][j][3];
            slo += v0 * (1.f - 2.f / (__expf(2.f * x0) + 1.f))
                 + v1 * (1.f - 2.f / (__expf(2.f * x1) + 1.f));
            shi += v0 * (1.f - 2.f / (__expf(2.f * x2) + 1.f))
                 + v1 * (1.f - 2.f / (__expf(2.f * x3) + 1.f));
        }
        slo += __shfl_xor_sync(0xffffffffu, slo, 1);
        slo += __shfl_xor_sync(0xffffffffu, slo, 2);
        shi += __shfl_xor_sync(0xffffffffu, shi, 1);
        shi += __shfl_xor_sync(0xffffffffu, shi, 2);
        if (gc == 0) {
            const int r = l0 + wm * 32 + i * 16 + gr;
            atomicAdd(&g_scores[(size_t)b * SEQ + r], slo);
            atomicAdd(&g_scores[(size_t)b * SEQ + r + 8], shi);
        }
    }
}

// ---------------------------------------------------------------------------
// Kernel 3: softmax over L per batch; zero-inits the context region of out.
// ---------------------------------------------------------------------------
__global__ void softmax_kernel(float* __restrict__ out) {
    __shared__ float sm[SEQ];
    __shared__ float red[256];
    const int b = blockIdx.x, tid = threadIdx.x;

    for (int d = tid; d < DIM; d += 256) out[b * DIM + d] = 0.f;

    float m = -1e30f;
    for (int l = tid; l < SEQ; l += 256) {
        float s = g_scores[b * SEQ + l];
        sm[l] = s;
        m = fmaxf(m, s);
    }
    red[tid] = m;
    __syncthreads();
    for (int o = 128; o; o >>= 1) {
        if (tid < o) red[tid] = fmaxf(red[tid], red[tid + o]);
        __syncthreads();
    }
    m = red[0];
    __syncthreads();

    float sum = 0.f;
    for (int l = tid; l < SEQ; l += 256) {
        float e = __expf(sm[l] - m);
        sm[l] = e;
        sum += e;
    }
    red[tid] = sum;
    __syncthreads();
    for (int o = 128; o; o >>= 1) {
        if (tid < o) red[tid] += red[tid + o];
        __syncthreads();
    }
    const float inv = 1.f / red[0];

    float* attn = out + BATCH * DIM;
    for (int l = tid; l < SEQ; l += 256) attn[b * SEQ + l] = sm[l] * inv;
}

// ---------------------------------------------------------------------------
// Kernel 4: context[b,d] += sum_{l in chunk} attn[b,l] * enc[b,l,d]  (fp32)
// Grid (BATCH, 32): 64 L-rows per block, atomicAdd fp32 partials.
// ---------------------------------------------------------------------------
__global__ void context_kernel(const float* __restrict__ enc,
                               float* __restrict__ out) {
    __shared__ float attn_sm[64];
    const int b = blockIdx.x, ch = blockIdx.y, tid = threadIdx.x;
    const int lbase = ch * 64;
    if (tid < 64) attn_sm[tid] = out[BATCH * DIM + (size_t)b * SEQ + lbase + tid];
    __syncthreads();

    float4 acc = make_float4(0.f, 0.f, 0.f, 0.f);
    const float4* ep = (const float4*)(enc + ((size_t)b * SEQ + lbase) * DIM) + tid;
    #pragma unroll 8
    for (int l = 0; l < 64; ++l) {
        float a = attn_sm[l];
        float4 v = ep[(size_t)l * (DIM / 4)];
        acc.x += a * v.x; acc.y += a * v.y;
        acc.z += a * v.z; acc.w += a * v.w;
    }
    float* dst = out + b * DIM + tid * 4;
    atomicAdd(dst + 0, acc.x);
    atomicAdd(dst + 1, acc.y);
    atomicAdd(dst + 2, acc.z);
    atomicAdd(dst + 3, acc.w);
}

// ---------------------------------------------------------------------------
extern "C" void kernel_launch(void* const* d_in, const int* in_sizes, int n_in,
                              void* d_out, int out_size) {
    const float* dh  = (const float*)d_in[0];   // [32,1,1024]
    const float* enc = (const float*)d_in[1];   // [32,2048,1024]
    const float* Ww  = (const float*)d_in[2];   // [1024,1024]
    const float* Wb  = (const float*)d_in[3];   // [1024]
    const float* Uw  = (const float*)d_in[4];   // [1024,1024]
    const float* Ub  = (const float*)d_in[5];   // [1024]
    const float* vw  = (const float*)d_in[6];   // [1,1024]
    float* out = (float*)d_out;                 // [32768 context | 65536 attn]

    (void)in_sizes; (void)n_in; (void)out_size;

    static bool attr_set = false;
    if (!attr_set) {
        cudaFuncSetAttribute(score_kernel,
                             cudaFuncAttributeMaxDynamicSharedMemorySize, SMEM_BYTES);
        attr_set = true;
    }

    prep_kernel<<<NUCONV_BLOCKS + NQP_BLOCKS, 256>>>(Uw, dh, Ww, Wb, Ub);

    dim3 sgrid(DIM / BN, SEQ / BM, BATCH);   // (4, 16, 32)
    score_kernel<<<sgrid, 512, SMEM_BYTES>>>(enc, vw);

    softmax_kernel<<<BATCH, 256>>>(out);

    dim3 cgrid(BATCH, 32);
    context_kernel<<<cgrid, 256>>>(enc, out);
}

// round 9
// speedup vs baseline: 1.2111x; 1.2111x over previous
#include <cuda_runtime.h>
#include <cuda_fp16.h>
#include <math.h>
#include <stdint.h>

#define BATCH 32
#define SEQ   2048
#define DIM   1024

#define BM 128
#define BN 256
#define BKH 64                      // k elems per chunk
#define KCHUNKS (DIM / BKH)         // 16
#define STAGES 3
#define ROWH 72                     // halfs per fp16 smem row (LDSM conflict-free)

#define A16_BYTES (BM * ROWH * 2)   // 18432 per stage
#define B16_BYTES (BN * ROWH * 2)   // 36864 per stage
#define OFF_A16(s) ((s) * A16_BYTES)
#define OFF_B16(s) (STAGES * A16_BYTES + (s) * B16_BYTES)
#define OFF_QV     (STAGES * (A16_BYTES + B16_BYTES))
#define SMEM_BYTES (OFF_QV + 2 * BN * 4)   // ~168 KB

// Scratch (static __device__ — no allocation inside kernel_launch)
__device__ float  g_q[BATCH * DIM];
__device__ float  g_scores[BATCH * SEQ];
__device__ __half g_enc_h[(size_t)BATCH * SEQ * DIM];  // written by score (n==0 blocks)
__device__ __half g_U_h[DIM * DIM];                    // fp16 copy of Uw (prep)

__device__ __forceinline__ uint32_t smem_u32(const void* p) {
    uint32_t a;
    asm("{ .reg .u64 t; cvta.to.shared.u64 t, %1; cvt.u32.u64 %0, t; }"
        : "=r"(a) : "l"(p));
    return a;
}

__device__ __forceinline__ void cp16(uint32_t dst, const void* src) {
    asm volatile("cp.async.cg.shared.global [%0], [%1], 16;"
                 :: "r"(dst), "l"(src) : "memory");
}
#define CP_COMMIT() asm volatile("cp.async.commit_group;" ::: "memory")
#define CP_WAIT(n)  asm volatile("cp.async.wait_group %0;" :: "n"(n) : "memory")

__device__ __forceinline__ void ldm_x4(uint32_t r[4], uint32_t addr) {
    asm volatile("ldmatrix.sync.aligned.m8n8.x4.shared.b16 {%0,%1,%2,%3}, [%4];"
                 : "=r"(r[0]), "=r"(r[1]), "=r"(r[2]), "=r"(r[3]) : "r"(addr));
}

__device__ __forceinline__ void mma_f16(float c[4], const uint32_t a[4], const uint32_t b[2]) {
    asm volatile(
        "mma.sync.aligned.m16n8k16.row.col.f32.f16.f16.f32 "
        "{%0,%1,%2,%3}, {%4,%5,%6,%7}, {%8,%9}, {%0,%1,%2,%3};"
        : "+f"(c[0]), "+f"(c[1]), "+f"(c[2]), "+f"(c[3])
        : "r"(a[0]), "r"(a[1]), "r"(a[2]), "r"(a[3]), "r"(b[0]), "r"(b[1]));
}

// ---------------------------------------------------------------------------
// Kernel 0 (tiny prep): U fp32->fp16, q' projection, zero g_scores.
// ---------------------------------------------------------------------------
#define NU8 ((size_t)DIM * DIM / 8)                    // 131072
#define NUCONV_BLOCKS ((unsigned)((NU8 + 255) / 256))  // 512
#define NQP_BLOCKS    (BATCH * DIM / 8)                // 4096

__global__ void prep_kernel(const float* __restrict__ Uw,
                            const float* __restrict__ dh,
                            const float* __restrict__ Ww,
                            const float* __restrict__ Wb,
                            const float* __restrict__ Ub) {
    if (blockIdx.x < NUCONV_BLOCKS) {
        size_t k = (size_t)blockIdx.x * 256 + threadIdx.x;
        if (k >= NU8) return;
        const float4* src = (const float4*)Uw;
        float4 f0 = src[k * 2], f1 = src[k * 2 + 1];
        __half2 h[4];
        h[0] = __floats2half2_rn(f0.x, f0.y);
        h[1] = __floats2half2_rn(f0.z, f0.w);
        h[2] = __floats2half2_rn(f1.x, f1.y);
        h[3] = __floats2half2_rn(f1.z, f1.w);
        ((uint4*)g_U_h)[k] = *(uint4*)h;
        return;
    }
    int qgid = (int)(blockIdx.x - NUCONV_BLOCKS) * 256 + threadIdx.x;
    if (qgid < BATCH * SEQ) g_scores[qgid] = 0.f;

    int warp = qgid >> 5;
    int lane = threadIdx.x & 31;
    if (warp >= BATCH * DIM) return;
    int b = warp / DIM, d = warp % DIM;
    const float* x = dh + b * DIM;
    const float* w = Ww + (size_t)d * DIM;
    float s = 0.f;
    #pragma unroll 4
    for (int e = lane; e < DIM; e += 32) s += x[e] * w[e];
    #pragma unroll
    for (int o = 16; o; o >>= 1) s += __shfl_xor_sync(0xffffffffu, s, o);
    if (lane == 0) g_q[warp] = s + Wb[d] + Ub[d];
}

// ---------------------------------------------------------------------------
// Kernel 2 (dominant): fp16 mma m16n8k16. A (enc fp32) loaded via LDG->regs
// two chunks ahead, converted AFTER the mma (latency hidden), STS'd next
// iter into a 3-stage fp16 tile. B (U fp16) cp.async 3-stage. n==0 blocks
// additionally STG the converted A to g_enc_h for the context kernel.
// Fused tanh*v epilogue, atomic score partials.
// Grid (4, 16, 32), 512 threads = 16 warps (4m x 4n), warp tile 32x64.
// ---------------------------------------------------------------------------
__global__ __launch_bounds__(512, 1)
void score_kernel(const float* __restrict__ enc,
                  const float* __restrict__ vw) {
    extern __shared__ char smc[];
    const uint32_t sb = smem_u32(smc);

    const int tid  = threadIdx.x;
    const int wid  = tid >> 5;
    const int lane = tid & 31;
    const int wm   = wid & 3;
    const int wn   = wid >> 2;
    const int gr   = lane >> 2;
    const int gc   = lane & 3;

    const int n0 = blockIdx.x * BN;
    const int l0 = blockIdx.y * BM;
    const int b  = blockIdx.z;
    const bool bx0 = (blockIdx.x == 0);

    const float*  Abase = enc + ((size_t)b * SEQ + l0) * DIM;
    const __half* Bbase = g_U_h + (size_t)n0 * DIM;

    float* q_sh = (float*)(smc + OFF_QV);
    float* v_sh = q_sh + BN;
    if (tid < BN) {
        q_sh[tid] = g_q[b * DIM + n0 + tid];
        v_sh[tid] = vw[n0 + tid];
    }

    // A mapping: 4 threads per row, 16 consecutive floats each
    const int arow = tid >> 2;            // 0..127
    const int aseg = (tid & 3) * 16;      // float offset within 64-wide chunk
    const float* Arow = Abase + (size_t)arow * DIM + aseg;
    __half* EncOut = g_enc_h + ((size_t)b * SEQ + l0 + arow) * DIM + aseg;
    const uint32_t a16_sts_off = (arow * ROWH + aseg) * 2;   // byte offset in A16 stage

    // B cp.async mapping: 8 x 16B segments per 128B row, 4 row-passes
    const int brow = tid >> 3;
    const int bseg = (tid & 7) * 8;

    float4 v[4];        // in-flight fp32 A chunk (lookahead 2)
    uint32_t a16[8];    // converted fp16 chunk pending STS (lookahead 1)

    // ---- prologue ----
    // chunk 0: LDG -> cvt -> STS A16[0]  (+ STG for context if n==0)
    #pragma unroll
    for (int j = 0; j < 4; j++) v[j] = *(const float4*)(Arow + j * 4);
    #pragma unroll
    for (int j = 0; j < 4; j++) {
        __half2 h0 = __floats2half2_rn(v[j].x, v[j].y);
        __half2 h1 = __floats2half2_rn(v[j].z, v[j].w);
        a16[j * 2]     = *(uint32_t*)&h0;
        a16[j * 2 + 1] = *(uint32_t*)&h1;
    }
    {
        uint4* d = (uint4*)(smc + OFF_A16(0) + a16_sts_off);
        d[0] = *(uint4*)&a16[0];
        d[1] = *(uint4*)&a16[4];
        if (bx0) {
            ((uint4*)EncOut)[0] = *(uint4*)&a16[0];
            ((uint4*)EncOut)[1] = *(uint4*)&a16[4];
        }
    }
    // chunk 1: LDG -> cvt -> hold in a16 (STS at iter 0), STG now if n==0
    #pragma unroll
    for (int j = 0; j < 4; j++) v[j] = *(const float4*)(Arow + BKH + j * 4);
    #pragma unroll
    for (int j = 0; j < 4; j++) {
        __half2 h0 = __floats2half2_rn(v[j].x, v[j].y);
        __half2 h1 = __floats2half2_rn(v[j].z, v[j].w);
        a16[j * 2]     = *(uint32_t*)&h0;
        a16[j * 2 + 1] = *(uint32_t*)&h1;
    }
    if (bx0) {
        ((uint4*)(EncOut + BKH))[0] = *(uint4*)&a16[0];
        ((uint4*)(EncOut + BKH))[1] = *(uint4*)&a16[4];
    }
    // B chunks 0,1 via cp.async (separate groups)
    #pragma unroll
    for (int s = 0; s < 2; s++) {
        const uint32_t bst = sb + OFF_B16(s);
        #pragma unroll
        for (int r = 0; r < 4; r++) {
            int row = brow + r * 64;
            cp16(bst + (row * ROWH + bseg) * 2, Bbase + (size_t)row * DIM + s * BKH + bseg);
        }
        CP_COMMIT();
    }

    // ldmatrix lane address components
    const int a_row = (lane & 7) + ((lane >> 3) & 1) * 8;
    const int a_col = ((lane >> 4) & 1) * 8;
    const int b_row = (lane & 7) + ((lane >> 4) & 1) * 8;
    const int b_col = ((lane >> 3) & 1) * 8;

    float acc[2][8][4];
    #pragma unroll
    for (int i = 0; i < 2; i++)
        #pragma unroll
        for (int j = 0; j < 8; j++)
            #pragma unroll
            for (int r = 0; r < 4; r++) acc[i][j][r] = 0.f;

    for (int kc = 0; kc < KCHUNKS; kc++) {
        CP_WAIT(1);          // B chunk kc arrived (group kc committed 2 iters ago)
        __syncthreads();     // fences A16/B16 stage rotation

        // STS pending fp16 chunk kc+1 -> A16[(kc+1)%3]
        if (kc + 1 < KCHUNKS) {
            uint4* d = (uint4*)(smc + OFF_A16((kc + 1) % STAGES) + a16_sts_off);
            d[0] = *(uint4*)&a16[0];
            d[1] = *(uint4*)&a16[4];
        }

        // LDG A chunk kc+2 (consumed after the mma below)
        const int kn = kc + 2;
        if (kn < KCHUNKS) {
            const float* src = Arow + kn * BKH;
            #pragma unroll
            for (int j = 0; j < 4; j++) v[j] = *(const float4*)(src + j * 4);
            // B chunk kc+2 cp.async
            const uint32_t bst = sb + OFF_B16(kn % STAGES);
            #pragma unroll
            for (int r = 0; r < 4; r++) {
                int row = brow + r * 64;
                cp16(bst + (row * ROWH + bseg) * 2,
                     Bbase + (size_t)row * DIM + kn * BKH + bseg);
            }
        }
        CP_COMMIT();   // always commit (possibly empty) to keep wait counts aligned

        // mma on chunk kc
        const uint32_t aoff = sb + OFF_A16(kc % STAGES) + ((wm * 32 + a_row) * ROWH + a_col) * 2;
        const uint32_t boff = sb + OFF_B16(kc % STAGES) + ((wn * 64 + b_row) * ROWH + b_col) * 2;

        #pragma unroll
        for (int ks = 0; ks < 4; ks++) {
            const int kb = ks * 16;
            uint32_t af[2][4], bq[4][4];
            #pragma unroll
            for (int p = 0; p < 4; p++)
                ldm_x4(bq[p], boff + (p * 16 * ROWH + kb) * 2);
            #pragma unroll
            for (int i = 0; i < 2; i++)
                ldm_x4(af[i], aoff + (i * 16 * ROWH + kb) * 2);
            #pragma unroll
            for (int i = 0; i < 2; i++)
                #pragma unroll
                for (int j = 0; j < 8; j++)
                    mma_f16(acc[i][j], af[i], &bq[j >> 1][(j & 1) * 2]);
        }

        // convert chunk kc+2 (LDG latency now fully drained by the mma block)
        if (kn < KCHUNKS) {
            #pragma unroll
            for (int j = 0; j < 4; j++) {
                __half2 h0 = __floats2half2_rn(v[j].x, v[j].y);
                __half2 h1 = __floats2half2_rn(v[j].z, v[j].w);
                a16[j * 2]     = *(uint32_t*)&h0;
                a16[j * 2 + 1] = *(uint32_t*)&h1;
            }
            if (bx0) {
                ((uint4*)(EncOut + kn * BKH))[0] = *(uint4*)&a16[0];
                ((uint4*)(EncOut + kn * BKH))[1] = *(uint4*)&a16[4];
            }
        }
    }

    // Fused epilogue: reduce 256-wide d-chunk through tanh * v
    #pragma unroll
    for (int i = 0; i < 2; i++) {
        float slo = 0.f, shi = 0.f;
        #pragma unroll
        for (int j = 0; j < 8; j++) {
            const int c = wn * 64 + j * 8 + gc * 2;
            const float v0 = v_sh[c], v1 = v_sh[c + 1];
            const float q0 = q_sh[c], q1 = q_sh[c + 1];
            float x0 = q0 + acc[i][j][0], x1 = q1 + acc[i][j][1];
            float x2 = q0 + acc[i][j][2], x3 = q1 + acc[i][j][3];
            slo += v0 * (1.f - 2.f / (__expf(2.f * x0) + 1.f))
                 + v1 * (1.f - 2.f / (__expf(2.f * x1) + 1.f));
            shi += v0 * (1.f - 2.f / (__expf(2.f * x2) + 1.f))
                 + v1 * (1.f - 2.f / (__expf(2.f * x3) + 1.f));
        }
        slo += __shfl_xor_sync(0xffffffffu, slo, 1);
        slo += __shfl_xor_sync(0xffffffffu, slo, 2);
        shi += __shfl_xor_sync(0xffffffffu, shi, 1);
        shi += __shfl_xor_sync(0xffffffffu, shi, 2);
        if (gc == 0) {
            const int r = l0 + wm * 32 + i * 16 + gr;
            atomicAdd(&g_scores[(size_t)b * SEQ + r], slo);
            atomicAdd(&g_scores[(size_t)b * SEQ + r + 8], shi);
        }
    }
}

// ---------------------------------------------------------------------------
// Kernel 3: softmax over L per batch; zero-inits the context region of out.
// ---------------------------------------------------------------------------
__global__ void softmax_kernel(float* __restrict__ out) {
    __shared__ float sm[SEQ];
    __shared__ float red[256];
    const int b = blockIdx.x, tid = threadIdx.x;

    for (int d = tid; d < DIM; d += 256) out[b * DIM + d] = 0.f;

    float m = -1e30f;
    for (int l = tid; l < SEQ; l += 256) {
        float s = g_scores[b * SEQ + l];
        sm[l] = s;
        m = fmaxf(m, s);
    }
    red[tid] = m;
    __syncthreads();
    for (int o = 128; o; o >>= 1) {
        if (tid < o) red[tid] = fmaxf(red[tid], red[tid + o]);
        __syncthreads();
    }
    m = red[0];
    __syncthreads();

    float sum = 0.f;
    for (int l = tid; l < SEQ; l += 256) {
        float e = __expf(sm[l] - m);
        sm[l] = e;
        sum += e;
    }
    red[tid] = sum;
    __syncthreads();
    for (int o = 128; o; o >>= 1) {
        if (tid < o) red[tid] += red[tid + o];
        __syncthreads();
    }
    const float inv = 1.f / red[0];

    float* attn = out + BATCH * DIM;
    for (int l = tid; l < SEQ; l += 256) attn[b * SEQ + l] = sm[l] * inv;
}

// ---------------------------------------------------------------------------
// Kernel 4: context[b,d] += sum_{l in chunk} attn[b,l] * enc_h[b,l,d]
// fp16 enc (written by score), fp32 accumulate + atomicAdd.
// Grid (BATCH, 32): 64 L-rows per block.
// ---------------------------------------------------------------------------
__global__ void context_kernel(float* __restrict__ out) {
    __shared__ float attn_sm[64];
    const int b = blockIdx.x, ch = blockIdx.y, tid = threadIdx.x;
    const int lbase = ch * 64;
    if (tid < 64) attn_sm[tid] = out[BATCH * DIM + (size_t)b * SEQ + lbase + tid];
    __syncthreads();

    float acc0 = 0.f, acc1 = 0.f, acc2 = 0.f, acc3 = 0.f;
    const __half* ep = g_enc_h + ((size_t)b * SEQ + lbase) * DIM + tid * 4;
    #pragma unroll 8
    for (int l = 0; l < 64; ++l) {
        float a = attn_sm[l];
        uint2 raw = *(const uint2*)(ep + (size_t)l * DIM);
        __half2 h0 = *(__half2*)&raw.x, h1 = *(__half2*)&raw.y;
        float2 f0 = __half22float2(h0), f1 = __half22float2(h1);
        acc0 += a * f0.x; acc1 += a * f0.y;
        acc2 += a * f1.x; acc3 += a * f1.y;
    }
    float* dst = out + b * DIM + tid * 4;
    atomicAdd(dst + 0, acc0);
    atomicAdd(dst + 1, acc1);
    atomicAdd(dst + 2, acc2);
    atomicAdd(dst + 3, acc3);
}

// ---------------------------------------------------------------------------
extern "C" void kernel_launch(void* const* d_in, const int* in_sizes, int n_in,
                              void* d_out, int out_size) {
    const float* dh  = (const float*)d_in[0];   // [32,1,1024]
    const float* enc = (const float*)d_in[1];   // [32,2048,1024]
    const float* Ww  = (const float*)d_in[2];   // [1024,1024]
    const float* Wb  = (const float*)d_in[3];   // [1024]
    const float* Uw  = (const float*)d_in[4];   // [1024,1024]
    const float* Ub  = (const float*)d_in[5];   // [1024]
    const float* vw  = (const float*)d_in[6];   // [1,1024]
    float* out = (float*)d_out;                 // [32768 context | 65536 attn]

    (void)in_sizes; (void)n_in; (void)out_size;

    static bool attr_set = false;
    if (!attr_set) {
        cudaFuncSetAttribute(score_kernel,
                             cudaFuncAttributeMaxDynamicSharedMemorySize, SMEM_BYTES);
        attr_set = true;
    }

    prep_kernel<<<NUCONV_BLOCKS + NQP_BLOCKS, 256>>>(Uw, dh, Ww, Wb, Ub);

    dim3 sgrid(DIM / BN, SEQ / BM, BATCH);   // (4, 16, 32)
    score_kernel<<<sgrid, 512, SMEM_BYTES>>>(enc, vw);

    softmax_kernel<<<BATCH, 256>>>(out);

    dim3 cgrid(BATCH, 32);
    context_kernel<<<cgrid, 256>>>(out);
}

// round 10
// speedup vs baseline: 1.2661x; 1.0454x over previous
#include <cuda_runtime.h>
#include <cuda_fp16.h>
#include <math.h>
#include <stdint.h>

#define BATCH 32
#define SEQ   2048
#define DIM   1024

#define BM 128
#define BN 256
#define BKH 64                      // k halfs per chunk (128 B)
#define KCHUNKS (DIM / BKH)         // 16 chunks per block (FULL K)
#define STAGES 3
#define ROWH 72                     // halfs per smem row (144 B stride, LDSM conflict-free)
#define A_HALFS (BM * ROWH)         // 9216
#define STAGE_HALFS ((BM + BN) * ROWH)   // 27648
#define SMEM_BYTES (STAGES * STAGE_HALFS * 2 + 2 * BN * 4)

// Scratch (static __device__ — no allocation inside kernel_launch)
__device__ float  g_q[BATCH * DIM];
__device__ float  g_scores[BATCH * SEQ];
__device__ __half g_enc_h[(size_t)BATCH * SEQ * DIM];   // fp16 copy of enc
__device__ __half g_U_h[DIM * DIM];                     // fp16 copy of Uw

__device__ __forceinline__ uint32_t smem_u32(const void* p) {
    uint32_t a;
    asm("{ .reg .u64 t; cvta.to.shared.u64 t, %1; cvt.u32.u64 %0, t; }"
        : "=r"(a) : "l"(p));
    return a;
}

__device__ __forceinline__ void cp16(uint32_t dst, const void* src) {
    asm volatile("cp.async.cg.shared.global [%0], [%1], 16;"
                 :: "r"(dst), "l"(src) : "memory");
}
#define CP_COMMIT() asm volatile("cp.async.commit_group;" ::: "memory")
#define CP_WAIT(n)  asm volatile("cp.async.wait_group %0;" :: "n"(n) : "memory")

__device__ __forceinline__ void ldm_x4(uint32_t r[4], uint32_t addr) {
    asm volatile("ldmatrix.sync.aligned.m8n8.x4.shared.b16 {%0,%1,%2,%3}, [%4];"
                 : "=r"(r[0]), "=r"(r[1]), "=r"(r[2]), "=r"(r[3]) : "r"(addr));
}

// fp16 accumulator variant: D/C are 2x f16x2 regs. Probe for double-rate pipe.
__device__ __forceinline__ void mma_f16acc(uint32_t c[2], const uint32_t a[4], const uint32_t b[2]) {
    asm volatile(
        "mma.sync.aligned.m16n8k16.row.col.f16.f16.f16.f16 "
        "{%0,%1}, {%2,%3,%4,%5}, {%6,%7}, {%0,%1};"
        : "+r"(c[0]), "+r"(c[1])
        : "r"(a[0]), "r"(a[1]), "r"(a[2]), "r"(a[3]), "r"(b[0]), "r"(b[1]));
}

// ---------------------------------------------------------------------------
// Kernel 0 (merged prep): fp32->fp16 convert of enc & Uw, q' projection, and
// zeroing of g_scores, all in one launch.
// ---------------------------------------------------------------------------
#define NENC8  ((size_t)BATCH * SEQ * DIM / 8)          // 8388608
#define NU8    ((size_t)DIM * DIM / 8)                  // 131072
#define NCONV_BLOCKS ((unsigned)((NENC8 + NU8 + 255) / 256))   // 33280
#define NQP_BLOCKS   (BATCH * DIM / 8)                  // 4096 (8 warps/block)

__global__ void prep_kernel(const float* __restrict__ enc,
                            const float* __restrict__ Uw,
                            const float* __restrict__ dh,
                            const float* __restrict__ Ww,
                            const float* __restrict__ Wb,
                            const float* __restrict__ Ub) {
    if (blockIdx.x < NCONV_BLOCKS) {
        size_t i = (size_t)blockIdx.x * 256 + threadIdx.x;
        const float4* src;
        uint4* dst;
        size_t k;
        if (i < NENC8)            { src = (const float4*)enc; dst = (uint4*)g_enc_h; k = i; }
        else if (i < NENC8 + NU8) { src = (const float4*)Uw;  dst = (uint4*)g_U_h;   k = i - NENC8; }
        else return;
        float4 f0 = src[k * 2], f1 = src[k * 2 + 1];
        __half2 h[4];
        h[0] = __floats2half2_rn(f0.x, f0.y);
        h[1] = __floats2half2_rn(f0.z, f0.w);
        h[2] = __floats2half2_rn(f1.x, f1.y);
        h[3] = __floats2half2_rn(f1.z, f1.w);
        dst[k] = *(uint4*)h;
        return;
    }
    // qproj part
    int qgid = (int)(blockIdx.x - NCONV_BLOCKS) * 256 + threadIdx.x;
    if (qgid < BATCH * SEQ) g_scores[qgid] = 0.f;

    int warp = qgid >> 5;
    int lane = threadIdx.x & 31;
    if (warp >= BATCH * DIM) return;
    int b = warp / DIM, d = warp % DIM;
    const float* x = dh + b * DIM;
    const float* w = Ww + (size_t)d * DIM;
    float s = 0.f;
    #pragma unroll 4
    for (int e = lane; e < DIM; e += 32) s += x[e] * w[e];
    #pragma unroll
    for (int o = 16; o; o >>= 1) s += __shfl_xor_sync(0xffffffffu, s, o);
    if (lane == 0) g_q[warp] = s + Wb[d] + Ub[d];
}

// ---------------------------------------------------------------------------
// Kernel 2 (dominant): fp16 mma m16n8k16 with FP16 ACCUMULATORS (full-K f16
// accumulation; precision budget: k-err ~5e-4 -> logit err ~1.7e-4).
// cp.async 3-stage single-sync multistage pipeline, ldmatrix frags.
// Tile 128(l) x 256(d) x full K=1024; fused tanh*v epilogue; atomic partials.
// Grid (4, 16, 32), 512 threads = 16 warps (4m x 4n), warp tile 32x64.
// ---------------------------------------------------------------------------
__global__ __launch_bounds__(512, 1)
void score_kernel(const float* __restrict__ vw) {
    extern __shared__ char smc[];
    const uint32_t sb = smem_u32(smc);

    const int tid  = threadIdx.x;
    const int wid  = tid >> 5;
    const int lane = tid & 31;
    const int wm   = wid & 3;
    const int wn   = wid >> 2;
    const int gr   = lane >> 2;
    const int gc   = lane & 3;

    const int n0 = blockIdx.x * BN;
    const int l0 = blockIdx.y * BM;
    const int b  = blockIdx.z;

    const __half* Abase = g_enc_h + ((size_t)b * SEQ + l0) * DIM;
    const __half* Bbase = g_U_h + (size_t)n0 * DIM;

    float* q_sh = (float*)(smc + STAGES * STAGE_HALFS * 2);
    float* v_sh = q_sh + BN;
    if (tid < BN) {
        q_sh[tid] = g_q[b * DIM + n0 + tid];
        v_sh[tid] = vw[n0 + tid];
    }

    // cp.async mapping: 8 x 16B segments per 128B chunk-row
    const int crow = tid >> 3;          // 0..63
    const int cseg = (tid & 7) * 8;     // half offset within row

    // prologue: fill stages 0 and 1
    #pragma unroll
    for (int s = 0; s < STAGES - 1; s++) {
        const int kf = s * BKH;
        const uint32_t stb = sb + s * STAGE_HALFS * 2;
        #pragma unroll
        for (int r = 0; r < 2; r++) {
            int row = crow + r * 64;
            cp16(stb + (row * ROWH + cseg) * 2, Abase + (size_t)row * DIM + kf + cseg);
        }
        #pragma unroll
        for (int r = 0; r < 4; r++) {
            int row = crow + r * 64;
            cp16(stb + (A_HALFS + row * ROWH + cseg) * 2,
                 Bbase + (size_t)row * DIM + kf + cseg);
        }
        CP_COMMIT();
    }

    // ldmatrix lane address components
    const int a_row = (lane & 7) + ((lane >> 3) & 1) * 8;
    const int a_col = ((lane >> 4) & 1) * 8;
    const int b_row = (lane & 7) + ((lane >> 4) & 1) * 8;
    const int b_col = ((lane >> 3) & 1) * 8;

    uint32_t hacc[2][8][2];   // f16x2 accumulators
    #pragma unroll
    for (int i = 0; i < 2; i++)
        #pragma unroll
        for (int j = 0; j < 8; j++) {
            hacc[i][j][0] = 0u;
            hacc[i][j][1] = 0u;
        }

    for (int kc = 0; kc < KCHUNKS; kc++) {
        CP_WAIT(1);
        __syncthreads();

        // refill stage (kc+2)%3 with chunk kc+2
        const int kn = kc + STAGES - 1;
        if (kn < KCHUNKS) {
            const int st_w = kn % STAGES;
            const int kf = kn * BKH;
            const uint32_t stw = sb + st_w * STAGE_HALFS * 2;
            #pragma unroll
            for (int r = 0; r < 2; r++) {
                int row = crow + r * 64;
                cp16(stw + (row * ROWH + cseg) * 2, Abase + (size_t)row * DIM + kf + cseg);
            }
            #pragma unroll
            for (int r = 0; r < 4; r++) {
                int row = crow + r * 64;
                cp16(stw + (A_HALFS + row * ROWH + cseg) * 2,
                     Bbase + (size_t)row * DIM + kf + cseg);
            }
        }
        CP_COMMIT();

        const uint32_t stb = sb + (kc % STAGES) * STAGE_HALFS * 2;
        const uint32_t aoff = stb + ((wm * 32 + a_row) * ROWH + a_col) * 2;
        const uint32_t boff = stb + (A_HALFS + (wn * 64 + b_row) * ROWH + b_col) * 2;

        #pragma unroll
        for (int ks = 0; ks < 4; ks++) {
            const int kb = ks * 16;
            uint32_t af[2][4], bq[4][4];
            #pragma unroll
            for (int p = 0; p < 4; p++)
                ldm_x4(bq[p], boff + (p * 16 * ROWH + kb) * 2);
            #pragma unroll
            for (int i = 0; i < 2; i++)
                ldm_x4(af[i], aoff + (i * 16 * ROWH + kb) * 2);
            #pragma unroll
            for (int i = 0; i < 2; i++)
                #pragma unroll
                for (int j = 0; j < 8; j++)
                    mma_f16acc(hacc[i][j], af[i], &bq[j >> 1][(j & 1) * 2]);
        }
    }

    // Fused epilogue: unpack f16 accs, reduce 256-wide d-chunk through tanh*v
    #pragma unroll
    for (int i = 0; i < 2; i++) {
        float slo = 0.f, shi = 0.f;
        #pragma unroll
        for (int j = 0; j < 8; j++) {
            const int c = wn * 64 + j * 8 + gc * 2;
            const float v0 = v_sh[c], v1 = v_sh[c + 1];
            const float q0 = q_sh[c], q1 = q_sh[c + 1];
            float2 p0 = __half22float2(*(__half2*)&hacc[i][j][0]);  // rows gr
            float2 p1 = __half22float2(*(__half2*)&hacc[i][j][1]);  // rows gr+8
            float x0 = q0 + p0.x, x1 = q1 + p0.y;
            float x2 = q0 + p1.x, x3 = q1 + p1.y;
            slo += v0 * (1.f - 2.f / (__expf(2.f * x0) + 1.f))
                 + v1 * (1.f - 2.f / (__expf(2.f * x1) + 1.f));
            shi += v0 * (1.f - 2.f / (__expf(2.f * x2) + 1.f))
                 + v1 * (1.f - 2.f / (__expf(2.f * x3) + 1.f));
        }
        slo += __shfl_xor_sync(0xffffffffu, slo, 1);
        slo += __shfl_xor_sync(0xffffffffu, slo, 2);
        shi += __shfl_xor_sync(0xffffffffu, shi, 1);
        shi += __shfl_xor_sync(0xffffffffu, shi, 2);
        if (gc == 0) {
            const int r = l0 + wm * 32 + i * 16 + gr;
            atomicAdd(&g_scores[(size_t)b * SEQ + r], slo);
            atomicAdd(&g_scores[(size_t)b * SEQ + r + 8], shi);
        }
    }
}

// ---------------------------------------------------------------------------
// Kernel 3: softmax over L per batch; zero-inits the context region of out.
// ---------------------------------------------------------------------------
__global__ void softmax_kernel(float* __restrict__ out) {
    __shared__ float sm[SEQ];
    __shared__ float red[256];
    const int b = blockIdx.x, tid = threadIdx.x;

    for (int d = tid; d < DIM; d += 256) out[b * DIM + d] = 0.f;

    float m = -1e30f;
    for (int l = tid; l < SEQ; l += 256) {
        float s = g_scores[b * SEQ + l];
        sm[l] = s;
        m = fmaxf(m, s);
    }
    red[tid] = m;
    __syncthreads();
    for (int o = 128; o; o >>= 1) {
        if (tid < o) red[tid] = fmaxf(red[tid], red[tid + o]);
        __syncthreads();
    }
    m = red[0];
    __syncthreads();

    float sum = 0.f;
    for (int l = tid; l < SEQ; l += 256) {
        float e = __expf(sm[l] - m);
        sm[l] = e;
        sum += e;
    }
    red[tid] = sum;
    __syncthreads();
    for (int o = 128; o; o >>= 1) {
        if (tid < o) red[tid] += red[tid + o];
        __syncthreads();
    }
    const float inv = 1.f / red[0];

    float* attn = out + BATCH * DIM;
    for (int l = tid; l < SEQ; l += 256) attn[b * SEQ + l] = sm[l] * inv;
}

// ---------------------------------------------------------------------------
// Kernel 4: context[b,d] += sum_{l in chunk} attn[b,l] * enc_h[b,l,d]
// fp16 enc, fp32 accumulate + atomicAdd. Grid (BATCH, 32): 64 rows/block.
// ---------------------------------------------------------------------------
__global__ void context_kernel(float* __restrict__ out) {
    __shared__ float attn_sm[64];
    const int b = blockIdx.x, ch = blockIdx.y, tid = threadIdx.x;
    const int lbase = ch * 64;
    if (tid < 64) attn_sm[tid] = out[BATCH * DIM + (size_t)b * SEQ + lbase + tid];
    __syncthreads();

    float acc0 = 0.f, acc1 = 0.f, acc2 = 0.f, acc3 = 0.f;
    const __half* ep = g_enc_h + ((size_t)b * SEQ + lbase) * DIM + tid * 4;
    #pragma unroll 8
    for (int l = 0; l < 64; ++l) {
        float a = attn_sm[l];
        uint2 raw = *(const uint2*)(ep + (size_t)l * DIM);
        __half2 h0 = *(__half2*)&raw.x, h1 = *(__half2*)&raw.y;
        float2 f0 = __half22float2(h0), f1 = __half22float2(h1);
        acc0 += a * f0.x; acc1 += a * f0.y;
        acc2 += a * f1.x; acc3 += a * f1.y;
    }
    float* dst = out + b * DIM + tid * 4;
    atomicAdd(dst + 0, acc0);
    atomicAdd(dst + 1, acc1);
    atomicAdd(dst + 2, acc2);
    atomicAdd(dst + 3, acc3);
}

// ---------------------------------------------------------------------------
extern "C" void kernel_launch(void* const* d_in, const int* in_sizes, int n_in,
                              void* d_out, int out_size) {
    const float* dh  = (const float*)d_in[0];   // [32,1,1024]
    const float* enc = (const float*)d_in[1];   // [32,2048,1024]
    const float* Ww  = (const float*)d_in[2];   // [1024,1024]
    const float* Wb  = (const float*)d_in[3];   // [1024]
    const float* Uw  = (const float*)d_in[4];   // [1024,1024]
    const float* Ub  = (const float*)d_in[5];   // [1024]
    const float* vw  = (const float*)d_in[6];   // [1,1024]
    float* out = (float*)d_out;                 // [32768 context | 65536 attn]

    (void)in_sizes; (void)n_in; (void)out_size;

    static bool attr_set = false;
    if (!attr_set) {
        cudaFuncSetAttribute(score_kernel,
                             cudaFuncAttributeMaxDynamicSharedMemorySize, SMEM_BYTES);
        attr_set = true;
    }

    prep_kernel<<<NCONV_BLOCKS + NQP_BLOCKS, 256>>>(enc, Uw, dh, Ww, Wb, Ub);

    dim3 sgrid(DIM / BN, SEQ / BM, BATCH);   // (4, 16, 32) — each block owns full K
    score_kernel<<<sgrid, 512, SMEM_BYTES>>>(vw);

    softmax_kernel<<<BATCH, 256>>>(out);

    dim3 cgrid(BATCH, 32);
    context_kernel<<<cgrid, 256>>>(out);
}

// round 11
// speedup vs baseline: 1.4697x; 1.1608x over previous
#include <cuda_runtime.h>
#include <cuda_fp16.h>
#include <math.h>
#include <stdint.h>

#define BATCH 32
#define SEQ   2048
#define DIM   1024

#define BM 128
#define BN 128
#define BKH 64                      // k halfs per chunk (128 B)
#define KCHUNKS (DIM / BKH)         // 16 chunks per block (FULL K)
#define STAGES 3
#define ROWH 72                     // halfs per smem row (144 B stride, LDSM conflict-free)
#define A_HALFS (BM * ROWH)         // 9216
#define STAGE_HALFS ((BM + BN) * ROWH)   // 18432
#define SMEM_BYTES (STAGES * STAGE_HALFS * 2 + 2 * BN * 4)   // ~111.6 KB

// Scratch (static __device__ — no allocation inside kernel_launch)
__device__ float  g_q[BATCH * DIM];
__device__ float  g_scores[BATCH * SEQ];
__device__ __half g_enc_h[(size_t)BATCH * SEQ * DIM];   // fp16 copy of enc
__device__ __half g_U_h[DIM * DIM];                     // fp16 copy of Uw

__device__ __forceinline__ uint32_t smem_u32(const void* p) {
    uint32_t a;
    asm("{ .reg .u64 t; cvta.to.shared.u64 t, %1; cvt.u32.u64 %0, t; }"
        : "=r"(a) : "l"(p));
    return a;
}

__device__ __forceinline__ void cp16(uint32_t dst, const void* src) {
    asm volatile("cp.async.cg.shared.global [%0], [%1], 16;"
                 :: "r"(dst), "l"(src) : "memory");
}
#define CP_COMMIT() asm volatile("cp.async.commit_group;" ::: "memory")
#define CP_WAIT(n)  asm volatile("cp.async.wait_group %0;" :: "n"(n) : "memory")

__device__ __forceinline__ void ldm_x4(uint32_t r[4], uint32_t addr) {
    asm volatile("ldmatrix.sync.aligned.m8n8.x4.shared.b16 {%0,%1,%2,%3}, [%4];"
                 : "=r"(r[0]), "=r"(r[1]), "=r"(r[2]), "=r"(r[3]) : "r"(addr));
}

__device__ __forceinline__ void mma_f16(float c[4], const uint32_t a[4], const uint32_t b[2]) {
    asm volatile(
        "mma.sync.aligned.m16n8k16.row.col.f32.f16.f16.f32 "
        "{%0,%1,%2,%3}, {%4,%5,%6,%7}, {%8,%9}, {%0,%1,%2,%3};"
        : "+f"(c[0]), "+f"(c[1]), "+f"(c[2]), "+f"(c[3])
        : "r"(a[0]), "r"(a[1]), "r"(a[2]), "r"(a[3]), "r"(b[0]), "r"(b[1]));
}

// ---------------------------------------------------------------------------
// Kernel 0 (merged prep): fp32->fp16 convert of enc & Uw, q' projection, and
// zeroing of g_scores, all in one launch.
// ---------------------------------------------------------------------------
#define NENC8  ((size_t)BATCH * SEQ * DIM / 8)          // 8388608
#define NU8    ((size_t)DIM * DIM / 8)                  // 131072
#define NCONV_BLOCKS ((unsigned)((NENC8 + NU8 + 255) / 256))   // 33280
#define NQP_BLOCKS   (BATCH * DIM / 8)                  // 4096 (8 warps/block)

__global__ void prep_kernel(const float* __restrict__ enc,
                            const float* __restrict__ Uw,
                            const float* __restrict__ dh,
                            const float* __restrict__ Ww,
                            const float* __restrict__ Wb,
                            const float* __restrict__ Ub) {
    if (blockIdx.x < NCONV_BLOCKS) {
        size_t i = (size_t)blockIdx.x * 256 + threadIdx.x;
        const float4* src;
        uint4* dst;
        size_t k;
        if (i < NENC8)            { src = (const float4*)enc; dst = (uint4*)g_enc_h; k = i; }
        else if (i < NENC8 + NU8) { src = (const float4*)Uw;  dst = (uint4*)g_U_h;   k = i - NENC8; }
        else return;
        float4 f0 = src[k * 2], f1 = src[k * 2 + 1];
        __half2 h[4];
        h[0] = __floats2half2_rn(f0.x, f0.y);
        h[1] = __floats2half2_rn(f0.z, f0.w);
        h[2] = __floats2half2_rn(f1.x, f1.y);
        h[3] = __floats2half2_rn(f1.z, f1.w);
        dst[k] = *(uint4*)h;
        return;
    }
    // qproj part
    int qgid = (int)(blockIdx.x - NCONV_BLOCKS) * 256 + threadIdx.x;
    if (qgid < BATCH * SEQ) g_scores[qgid] = 0.f;

    int warp = qgid >> 5;
    int lane = threadIdx.x & 31;
    if (warp >= BATCH * DIM) return;
    int b = warp / DIM, d = warp % DIM;
    const float* x = dh + b * DIM;
    const float* w = Ww + (size_t)d * DIM;
    float s = 0.f;
    #pragma unroll 4
    for (int e = lane; e < DIM; e += 32) s += x[e] * w[e];
    #pragma unroll
    for (int o = 16; o; o >>= 1) s += __shfl_xor_sync(0xffffffffu, s, o);
    if (lane == 0) g_q[warp] = s + Wb[d] + Ub[d];
}

// ---------------------------------------------------------------------------
// Kernel 2 (dominant): fp16 mma m16n8k16, f32 acc, cp.async 3-stage
// single-sync pipeline, ldmatrix frags. SMALL TILES to kill wave
// quantization: 128(l) x 128(d) x full K, 256 threads, 2 blocks/SM.
// Grid (8, 16, 32) = 4096 blocks (~14 waves of 296 slots -> ~1% tail).
// 8 warps = 4m x 2n, warp tile 32x64 (same mma:LDSM ratio as before).
// ---------------------------------------------------------------------------
__global__ __launch_bounds__(256, 2)
void score_kernel(const float* __restrict__ vw) {
    extern __shared__ char smc[];
    const uint32_t sb = smem_u32(smc);

    const int tid  = threadIdx.x;
    const int wid  = tid >> 5;
    const int lane = tid & 31;
    const int wm   = wid & 3;          // 0..3 -> m offset wm*32
    const int wn   = wid >> 2;         // 0..1 -> n offset wn*64
    const int gr   = lane >> 2;
    const int gc   = lane & 3;

    const int n0 = blockIdx.x * BN;
    const int l0 = blockIdx.y * BM;
    const int b  = blockIdx.z;

    const __half* Abase = g_enc_h + ((size_t)b * SEQ + l0) * DIM;
    const __half* Bbase = g_U_h + (size_t)n0 * DIM;

    float* q_sh = (float*)(smc + STAGES * STAGE_HALFS * 2);
    float* v_sh = q_sh + BN;
    if (tid < BN) {
        q_sh[tid] = g_q[b * DIM + n0 + tid];
        v_sh[tid] = vw[n0 + tid];
    }

    // cp.async mapping: 8 x 16B segments per 128B chunk-row; 256 threads
    // cover 32 rows per pass -> 4 passes each for A(128) and B(128).
    const int crow = tid >> 3;          // 0..31
    const int cseg = (tid & 7) * 8;     // half offset within row

    // prologue: fill stages 0 and 1
    #pragma unroll
    for (int s = 0; s < STAGES - 1; s++) {
        const int kf = s * BKH;
        const uint32_t stb = sb + s * STAGE_HALFS * 2;
        #pragma unroll
        for (int r = 0; r < 4; r++) {
            int row = crow + r * 32;
            cp16(stb + (row * ROWH + cseg) * 2, Abase + (size_t)row * DIM + kf + cseg);
        }
        #pragma unroll
        for (int r = 0; r < 4; r++) {
            int row = crow + r * 32;
            cp16(stb + (A_HALFS + row * ROWH + cseg) * 2,
                 Bbase + (size_t)row * DIM + kf + cseg);
        }
        CP_COMMIT();
    }

    // ldmatrix lane address components
    const int a_row = (lane & 7) + ((lane >> 3) & 1) * 8;
    const int a_col = ((lane >> 4) & 1) * 8;
    const int b_row = (lane & 7) + ((lane >> 4) & 1) * 8;
    const int b_col = ((lane >> 3) & 1) * 8;

    float acc[2][8][4];
    #pragma unroll
    for (int i = 0; i < 2; i++)
        #pragma unroll
        for (int j = 0; j < 8; j++)
            #pragma unroll
            for (int r = 0; r < 4; r++) acc[i][j][r] = 0.f;

    for (int kc = 0; kc < KCHUNKS; kc++) {
        CP_WAIT(1);
        __syncthreads();

        // refill stage (kc+2)%3 with chunk kc+2
        const int kn = kc + STAGES - 1;
        if (kn < KCHUNKS) {
            const int st_w = kn % STAGES;
            const int kf = kn * BKH;
            const uint32_t stw = sb + st_w * STAGE_HALFS * 2;
            #pragma unroll
            for (int r = 0; r < 4; r++) {
                int row = crow + r * 32;
                cp16(stw + (row * ROWH + cseg) * 2, Abase + (size_t)row * DIM + kf + cseg);
            }
            #pragma unroll
            for (int r = 0; r < 4; r++) {
                int row = crow + r * 32;
                cp16(stw + (A_HALFS + row * ROWH + cseg) * 2,
                     Bbase + (size_t)row * DIM + kf + cseg);
            }
        }
        CP_COMMIT();

        const uint32_t stb = sb + (kc % STAGES) * STAGE_HALFS * 2;
        const uint32_t aoff = stb + ((wm * 32 + a_row) * ROWH + a_col) * 2;
        const uint32_t boff = stb + (A_HALFS + (wn * 64 + b_row) * ROWH + b_col) * 2;

        #pragma unroll
        for (int ks = 0; ks < 4; ks++) {
            const int kb = ks * 16;
            uint32_t af[2][4], bq[4][4];
            #pragma unroll
            for (int p = 0; p < 4; p++)
                ldm_x4(bq[p], boff + (p * 16 * ROWH + kb) * 2);
            #pragma unroll
            for (int i = 0; i < 2; i++)
                ldm_x4(af[i], aoff + (i * 16 * ROWH + kb) * 2);
            #pragma unroll
            for (int i = 0; i < 2; i++)
                #pragma unroll
                for (int j = 0; j < 8; j++)
                    mma_f16(acc[i][j], af[i], &bq[j >> 1][(j & 1) * 2]);
        }
    }

    // Fused epilogue: reduce 128-wide d-chunk through tanh * v
    #pragma unroll
    for (int i = 0; i < 2; i++) {
        float slo = 0.f, shi = 0.f;
        #pragma unroll
        for (int j = 0; j < 8; j++) {
            const int c = wn * 64 + j * 8 + gc * 2;
            const float v0 = v_sh[c], v1 = v_sh[c + 1];
            const float q0 = q_sh[c], q1 = q_sh[c + 1];
            float x0 = q0 + acc[i][j][0], x1 = q1 + acc[i][j][1];
            float x2 = q0 + acc[i][j][2], x3 = q1 + acc[i][j][3];
            slo += v0 * (1.f - 2.f / (__expf(2.f * x0) + 1.f))
                 + v1 * (1.f - 2.f / (__expf(2.f * x1) + 1.f));
            shi += v0 * (1.f - 2.f / (__expf(2.f * x2) + 1.f))
                 + v1 * (1.f - 2.f / (__expf(2.f * x3) + 1.f));
        }
        slo += __shfl_xor_sync(0xffffffffu, slo, 1);
        slo += __shfl_xor_sync(0xffffffffu, slo, 2);
        shi += __shfl_xor_sync(0xffffffffu, shi, 1);
        shi += __shfl_xor_sync(0xffffffffu, shi, 2);
        if (gc == 0) {
            const int r = l0 + wm * 32 + i * 16 + gr;
            atomicAdd(&g_scores[(size_t)b * SEQ + r], slo);
            atomicAdd(&g_scores[(size_t)b * SEQ + r + 8], shi);
        }
    }
}

// ---------------------------------------------------------------------------
// Kernel 3: softmax over L per batch; zero-inits the context region of out.
// ---------------------------------------------------------------------------
__global__ void softmax_kernel(float* __restrict__ out) {
    __shared__ float sm[SEQ];
    __shared__ float red[256];
    const int b = blockIdx.x, tid = threadIdx.x;

    for (int d = tid; d < DIM; d += 256) out[b * DIM + d] = 0.f;

    float m = -1e30f;
    for (int l = tid; l < SEQ; l += 256) {
        float s = g_scores[b * SEQ + l];
        sm[l] = s;
        m = fmaxf(m, s);
    }
    red[tid] = m;
    __syncthreads();
    for (int o = 128; o; o >>= 1) {
        if (tid < o) red[tid] = fmaxf(red[tid], red[tid + o]);
        __syncthreads();
    }
    m = red[0];
    __syncthreads();

    float sum = 0.f;
    for (int l = tid; l < SEQ; l += 256) {
        float e = __expf(sm[l] - m);
        sm[l] = e;
        sum += e;
    }
    red[tid] = sum;
    __syncthreads();
    for (int o = 128; o; o >>= 1) {
        if (tid < o) red[tid] += red[tid + o];
        __syncthreads();
    }
    const float inv = 1.f / red[0];

    float* attn = out + BATCH * DIM;
    for (int l = tid; l < SEQ; l += 256) attn[b * SEQ + l] = sm[l] * inv;
}

// ---------------------------------------------------------------------------
// Kernel 4: context[b,d] += sum_{l in chunk} attn[b,l] * enc_h[b,l,d]
// fp16 enc, fp32 accumulate + atomicAdd. Grid (BATCH, 32): 64 rows/block.
// ---------------------------------------------------------------------------
__global__ void context_kernel(float* __restrict__ out) {
    __shared__ float attn_sm[64];
    const int b = blockIdx.x, ch = blockIdx.y, tid = threadIdx.x;
    const int lbase = ch * 64;
    if (tid < 64) attn_sm[tid] = out[BATCH * DIM + (size_t)b * SEQ + lbase + tid];
    __syncthreads();

    float acc0 = 0.f, acc1 = 0.f, acc2 = 0.f, acc3 = 0.f;
    const __half* ep = g_enc_h + ((size_t)b * SEQ + lbase) * DIM + tid * 4;
    #pragma unroll 8
    for (int l = 0; l < 64; ++l) {
        float a = attn_sm[l];
        uint2 raw = *(const uint2*)(ep + (size_t)l * DIM);
        __half2 h0 = *(__half2*)&raw.x, h1 = *(__half2*)&raw.y;
        float2 f0 = __half22float2(h0), f1 = __half22float2(h1);
        acc0 += a * f0.x; acc1 += a * f0.y;
        acc2 += a * f1.x; acc3 += a * f1.y;
    }
    float* dst = out + b * DIM + tid * 4;
    atomicAdd(dst + 0, acc0);
    atomicAdd(dst + 1, acc1);
    atomicAdd(dst + 2, acc2);
    atomicAdd(dst + 3, acc3);
}

// ---------------------------------------------------------------------------
extern "C" void kernel_launch(void* const* d_in, const int* in_sizes, int n_in,
                              void* d_out, int out_size) {
    const float* dh  = (const float*)d_in[0];   // [32,1,1024]
    const float* enc = (const float*)d_in[1];   // [32,2048,1024]
    const float* Ww  = (const float*)d_in[2];   // [1024,1024]
    const float* Wb  = (const float*)d_in[3];   // [1024]
    const float* Uw  = (const float*)d_in[4];   // [1024,1024]
    const float* Ub  = (const float*)d_in[5];   // [1024]
    const float* vw  = (const float*)d_in[6];   // [1,1024]
    float* out = (float*)d_out;                 // [32768 context | 65536 attn]

    (void)in_sizes; (void)n_in; (void)out_size;

    static bool attr_set = false;
    if (!attr_set) {
        cudaFuncSetAttribute(score_kernel,
                             cudaFuncAttributeMaxDynamicSharedMemorySize, SMEM_BYTES);
        attr_set = true;
    }

    prep_kernel<<<NCONV_BLOCKS + NQP_BLOCKS, 256>>>(enc, Uw, dh, Ww, Wb, Ub);

    dim3 sgrid(DIM / BN, SEQ / BM, BATCH);   // (8, 16, 32) = 4096 blocks
    score_kernel<<<sgrid, 256, SMEM_BYTES>>>(vw);

    softmax_kernel<<<BATCH, 256>>>(out);

    dim3 cgrid(BATCH, 32);
    context_kernel<<<cgrid, 256>>>(out);
}